// round 14
// baseline (speedup 1.0000x reference)
#include <cuda_runtime.h>
#include <cuda_fp16.h>
#include <mma.h>
#include <math.h>
#include <stdint.h>

using namespace nvcuda;

// ---------------- problem constants ----------------
#define RESO 56
#define WS   7
#define CDIM 128
#define NHEAD 4
#define HDIM 32
#define HID  512
#define BATCH 32
#define NTOK (BATCH * RESO * RESO)      // 100352
#define NWIN (BATCH * 8 * 8)            // 2048 windows
#define TWIN 49

#define W_QKV_N 49152
#define W_PROJ_N 16384
#define W_W1_N 65536
#define W_W2_N 65536
#define W_TOTAL (W_QKV_N + W_PROJ_N + W_W1_N + W_W2_N)
#define W_BLOCKS ((W_TOTAL + 255) / 256)          // 769
#define LN_BLOCKS ((NTOK * 32) / 256)             // 12544

// ---------------- device scratch ----------------
__device__ __half g_lnh[(size_t)NTOK * CDIM];
__device__ __half g_qkvh[(size_t)NTOK * 3 * CDIM];
__device__ __half g_oh [(size_t)NTOK * CDIM];
__device__ __half g_x2h[(size_t)NTOK * CDIM];
__device__ __half g_wTh[W_TOTAL];

__device__ __forceinline__ uint32_t smem_u32(const void* p) {
    uint32_t a;
    asm("{ .reg .u64 t; cvta.to.shared.u64 t, %1; cvt.u32.u64 %0, t; }" : "=r"(a) : "l"(p));
    return a;
}
__device__ __forceinline__ void cp_async16(uint32_t saddr, const void* gaddr) {
    asm volatile("cp.async.ca.shared.global [%0], [%1], 16;" :: "r"(saddr), "l"(gaddr));
}
#define CP_COMMIT() asm volatile("cp.async.commit_group;" ::: "memory")
#define CP_WAIT(n)  asm volatile("cp.async.wait_group %0;" :: "n"(n) : "memory")

__device__ __forceinline__ void store_half4(__half* dst, float a, float b, float c, float d) {
    __half2 h01 = __floats2half2_rn(a, b);
    __half2 h23 = __floats2half2_rn(c, d);
    uint2 u;
    u.x = *(uint32_t*)&h01;
    u.y = *(uint32_t*)&h23;
    *(uint2*)dst = u;
}

// ---------------- fused prep: weight->half + LN1->half ----------------
__global__ void prep_kernel(const float* __restrict__ w0, const float* __restrict__ w1,
                            const float* __restrict__ w2, const float* __restrict__ w3,
                            __half* __restrict__ WT,
                            const float* __restrict__ x, const float* __restrict__ g,
                            const float* __restrict__ b, __half* __restrict__ out)
{
    if (blockIdx.x < W_BLOCKS) {
        int idx = blockIdx.x * 256 + threadIdx.x;
        if (idx >= W_TOTAL) return;
        float v;
        if (idx < W_QKV_N)                          v = w0[idx];
        else if (idx < W_QKV_N + W_PROJ_N)          v = w1[idx - W_QKV_N];
        else if (idx < W_QKV_N + W_PROJ_N + W_W1_N) v = w2[idx - W_QKV_N - W_PROJ_N];
        else                                        v = w3[idx - W_QKV_N - W_PROJ_N - W_W1_N];
        WT[idx] = __float2half_rn(v);
        return;
    }
    int gwarp = ((blockIdx.x - W_BLOCKS) * 256 + threadIdx.x) >> 5;
    int lane  = threadIdx.x & 31;
    if (gwarp >= NTOK) return;
    float4 v = ((const float4*)(x + (size_t)gwarp * CDIM))[lane];
    float s  = v.x + v.y + v.z + v.w;
    float ss = v.x*v.x + v.y*v.y + v.z*v.z + v.w*v.w;
    #pragma unroll
    for (int off = 16; off; off >>= 1) {
        s  += __shfl_xor_sync(0xffffffffu, s,  off);
        ss += __shfl_xor_sync(0xffffffffu, ss, off);
    }
    float mean = s * (1.0f / CDIM);
    float var  = ss * (1.0f / CDIM) - mean * mean;
    float rstd = rsqrtf(var + 1e-5f);
    float4 gg = ((const float4*)g)[lane];
    float4 bb = ((const float4*)b)[lane];
    store_half4(out + (size_t)gwarp * CDIM + lane * 4,
                (v.x - mean) * rstd * gg.x + bb.x,
                (v.y - mean) * rstd * gg.y + bb.y,
                (v.z - mean) * rstd * gg.z + bb.z,
                (v.w - mean) * rstd * gg.w + bb.w);
}

// ---------------- fp16 WMMA GEMM (R11/R13 proven core) ----------------------
enum { EPI_BIAS = 0, EPI_RES_LN2 = 3 };

#define AH_STRIDE 40
#define BH_STRIDE 136
#define C_STRIDE  132
#define ABUFH (128 * AH_STRIDE * 2)     // 10240 B
#define BBUFH (32 * BH_STRIDE * 2)      // 8704 B
#define SMEM_BYTES (128 * C_STRIDE * 4) // 67584 B

template <int EPI>
__global__ void __launch_bounds__(256, 2)
tc_gemm(const __half* __restrict__ A, const __half* __restrict__ B,
        const float* __restrict__ bias, const float* __restrict__ res,
        __half* __restrict__ Ch, int N, int K,
        const float* __restrict__ lng, const float* __restrict__ lnb,
        __half* __restrict__ C2)
{
    extern __shared__ char smem[];
    uint32_t sbase = smem_u32(smem);
    const int tid = threadIdx.x;
    const int wid = tid >> 5;
    const int warpM = wid & 1;
    const int warpN = wid >> 1;
    const int M0 = blockIdx.y * 128;
    const int N0 = blockIdx.x * 128;

    const __half* Abase = A + (size_t)M0 * K;
    const __half* Bbase = B + N0;
    const int nchunk = K >> 5;

    wmma::fragment<wmma::accumulator, 16, 16, 16, float> acc[4][2];
    #pragma unroll
    for (int i = 0; i < 4; i++)
        #pragma unroll
        for (int j = 0; j < 2; j++) wmma::fill_fragment(acc[i][j], 0.0f);

    auto load_chunk = [&](int c) {
        int buf = c & 1;
        uint32_t sa = sbase + buf * ABUFH;
        uint32_t sb = sbase + 2 * ABUFH + buf * BBUFH;
        int k0 = c << 5;
        #pragma unroll
        for (int q = 0; q < 2; q++) {
            int e = tid + q * 256;
            int row = e >> 2, c8 = (e & 3) * 8;
            cp_async16(sa + (row * AH_STRIDE + c8) * 2,
                       Abase + (size_t)row * K + k0 + c8);
        }
        #pragma unroll
        for (int q = 0; q < 2; q++) {
            int e = tid + q * 256;
            int row = e >> 4, c8 = (e & 15) * 8;
            cp_async16(sb + (row * BH_STRIDE + c8) * 2,
                       Bbase + (size_t)(k0 + row) * N + c8);
        }
    };

    load_chunk(0);
    CP_COMMIT();

    for (int c = 0; c < nchunk; c++) {
        if (c + 1 < nchunk) {
            load_chunk(c + 1);
            CP_COMMIT();
            CP_WAIT(1);
        } else {
            CP_WAIT(0);
        }
        __syncthreads();

        int buf = c & 1;
        const __half* As = (const __half*)(smem + buf * ABUFH);
        const __half* Bs = (const __half*)(smem + 2 * ABUFH + buf * BBUFH);
        #pragma unroll
        for (int ks = 0; ks < 2; ks++) {
            wmma::fragment<wmma::matrix_a, 16, 16, 16, __half, wmma::row_major> af[4];
            wmma::fragment<wmma::matrix_b, 16, 16, 16, __half, wmma::row_major> bf[2];
            #pragma unroll
            for (int i = 0; i < 4; i++)
                wmma::load_matrix_sync(af[i],
                    As + (warpM * 64 + i * 16) * AH_STRIDE + ks * 16, AH_STRIDE);
            #pragma unroll
            for (int j = 0; j < 2; j++)
                wmma::load_matrix_sync(bf[j],
                    Bs + (ks * 16) * BH_STRIDE + warpN * 32 + j * 16, BH_STRIDE);
            #pragma unroll
            for (int i = 0; i < 4; i++)
                #pragma unroll
                for (int j = 0; j < 2; j++)
                    wmma::mma_sync(acc[i][j], af[i], bf[j], acc[i][j]);
        }
        __syncthreads();
    }

    float* Cs = (float*)smem;
    #pragma unroll
    for (int i = 0; i < 4; i++)
        #pragma unroll
        for (int j = 0; j < 2; j++)
            wmma::store_matrix_sync(
                Cs + (warpM * 64 + i * 16) * C_STRIDE + warpN * 32 + j * 16,
                acc[i][j], C_STRIDE, wmma::mem_row_major);
    __syncthreads();

    #pragma unroll
    for (int e0 = 0; e0 < 16; e0++) {
        int e = tid + e0 * 256;
        int row = e >> 5;
        int c4  = (e & 31) * 4;
        size_t roff = (size_t)(M0 + row) * N + N0 + c4;
        float v[4];
        #pragma unroll
        for (int q = 0; q < 4; q++) {
            float t = Cs[row * C_STRIDE + c4 + q] + __ldg(bias + N0 + c4 + q);
            if (EPI == EPI_RES_LN2) t += res[roff + q];
            v[q] = t;
        }
        store_half4(Ch + roff, v[0], v[1], v[2], v[3]);
        if (EPI == EPI_RES_LN2) {
            float s  = v[0] + v[1] + v[2] + v[3];
            float ss = v[0]*v[0] + v[1]*v[1] + v[2]*v[2] + v[3]*v[3];
            #pragma unroll
            for (int off = 16; off; off >>= 1) {
                s  += __shfl_xor_sync(0xffffffffu, s,  off);
                ss += __shfl_xor_sync(0xffffffffu, ss, off);
            }
            float mean = s * (1.0f / CDIM);
            float var  = ss * (1.0f / CDIM) - mean * mean;
            float rstd = rsqrtf(var + 1e-5f);
            store_half4(C2 + roff,
                        (v[0] - mean) * rstd * __ldg(lng + c4 + 0) + __ldg(lnb + c4 + 0),
                        (v[1] - mean) * rstd * __ldg(lng + c4 + 1) + __ldg(lnb + c4 + 1),
                        (v[2] - mean) * rstd * __ldg(lng + c4 + 2) + __ldg(lnb + c4 + 2),
                        (v[3] - mean) * rstd * __ldg(lng + c4 + 3) + __ldg(lnb + c4 + 3));
        }
    }
}

// ---------------- fused MLP: out = x2h + gelu(lnh@w1+b1)@w2 + b2 -----------
// 512 threads (16 warps), 1 CTA/SM, grid 784. Hidden dim in 8 chunks of 64.
// smem (halves unless noted):
//   As : 128 x 136        @      0   (34816 B)  [epilogue fp32 staging reuses 0..67584]
//   W1 : 2 x (128 x 72)   @  34816   (36864 B)
//   H1f: 128 x 68 fp32    @  71680   (34816 B)
//   H1 : 128 x 72         @ 106496   (18432 B)
//   W2 : 64 x 136         @ 124928   (17408 B)
#define FM_AS   0
#define FM_W1   34816
#define FM_W1SZ 18432
#define FM_H1F  71680
#define FM_H1   106496
#define FM_W2   124928
#define FM_SMEM 142336

__global__ void __launch_bounds__(512, 1)
fused_mlp(const __half* __restrict__ A, const __half* __restrict__ w1,
          const float* __restrict__ b1, const __half* __restrict__ w2,
          const float* __restrict__ b2, const __half* __restrict__ resh,
          float* __restrict__ out)
{
    extern __shared__ char smc[];
    uint32_t sbase = smem_u32(smc);
    const __half* As = (const __half*)(smc + FM_AS);
    float*  H1f = (float*)(smc + FM_H1F);
    __half* H1  = (__half*)(smc + FM_H1);
    const __half* W2s = (const __half*)(smc + FM_W2);

    const int tid = threadIdx.x;
    const int wid = tid >> 5;
    const int wM  = wid & 7;            // 16-row slice (GEMM1 & GEMM2)
    const int wN  = wid >> 3;           // 0..1
    const int M0 = blockIdx.x * 128;
    const __half* Abase = A + (size_t)M0 * CDIM;

    wmma::fragment<wmma::accumulator, 16, 16, 16, float> acc2[4];
    #pragma unroll
    for (int j = 0; j < 4; j++) wmma::fill_fragment(acc2[j], 0.0f);

    // prologue: A tile (2048 chunks), w1[0] (1024), w2[0] (1024)
    #pragma unroll
    for (int q = 0; q < 4; q++) {
        int e = tid + q * 512;
        int row = e >> 4, c8 = (e & 15) * 8;
        cp_async16(sbase + FM_AS + (row * 136 + c8) * 2,
                   Abase + (size_t)row * CDIM + c8);
    }
    CP_COMMIT();
    auto load_w1 = [&](int c) {
        uint32_t dst = sbase + FM_W1 + (c & 1) * FM_W1SZ;
        #pragma unroll
        for (int q = 0; q < 2; q++) {
            int e = tid + q * 512;
            int row = e >> 3, c8 = (e & 7) * 8;
            cp_async16(dst + (row * 72 + c8) * 2,
                       w1 + (size_t)row * HID + c * 64 + c8);
        }
    };
    auto load_w2 = [&](int c) {
        #pragma unroll
        for (int q = 0; q < 2; q++) {
            int e = tid + q * 512;
            int row = e >> 4, c8 = (e & 15) * 8;
            cp_async16(sbase + FM_W2 + (row * 136 + c8) * 2,
                       w2 + (size_t)(c * 64 + row) * CDIM + c8);
        }
    };
    load_w1(0); CP_COMMIT();
    load_w2(0); CP_COMMIT();

    for (int c = 0; c < 8; c++) {
        CP_WAIT(1);                 // A + w1[c] landed (w2[c] may be pending)
        __syncthreads();

        // GEMM1: H1f_chunk = As @ w1[c]  (128 x 64 x 128)
        const __half* W1s = (const __half*)(smc + FM_W1 + (c & 1) * FM_W1SZ);
        wmma::fragment<wmma::accumulator, 16, 16, 16, float> acc1[2];
        wmma::fill_fragment(acc1[0], 0.0f);
        wmma::fill_fragment(acc1[1], 0.0f);
        #pragma unroll
        for (int kt = 0; kt < 8; kt++) {
            wmma::fragment<wmma::matrix_a, 16, 16, 16, __half, wmma::row_major> af;
            wmma::load_matrix_sync(af, As + (wM * 16) * 136 + kt * 16, 136);
            #pragma unroll
            for (int j = 0; j < 2; j++) {
                wmma::fragment<wmma::matrix_b, 16, 16, 16, __half, wmma::row_major> bf;
                wmma::load_matrix_sync(bf, W1s + (kt * 16) * 72 + wN * 32 + j * 16, 72);
                wmma::mma_sync(acc1[j], af, bf, acc1[j]);
            }
        }
        // prefetch w1[c+1] (overlaps gelu + GEMM2)
        if (c < 7) { load_w1(c + 1); CP_COMMIT(); }

        #pragma unroll
        for (int j = 0; j < 2; j++)
            wmma::store_matrix_sync(H1f + (wM * 16) * 68 + wN * 32 + j * 16,
                                    acc1[j], 68, wmma::mem_row_major);
        __syncthreads();

        // gelu + bias -> H1 (half)
        #pragma unroll
        for (int q = 0; q < 4; q++) {
            int e = tid + q * 512;
            int row = e >> 4, c4 = (e & 15) * 4;
            const float* src = H1f + row * 68 + c4;
            float4 h = *(const float4*)src;
            float hv[4] = {h.x, h.y, h.z, h.w};
            #pragma unroll
            for (int u = 0; u < 4; u++) {
                float t = hv[u] + __ldg(b1 + c * 64 + c4 + u);
                hv[u] = 0.5f * t * (1.0f + erff(t * 0.70710678118654752f));
            }
            store_half4(H1 + row * 72 + c4, hv[0], hv[1], hv[2], hv[3]);
        }
        // ensure w2[c] landed (w1[c+1] may still be in flight)
        if (c < 7) { CP_WAIT(1); } else { CP_WAIT(0); }
        __syncthreads();

        // GEMM2: acc2 += H1 @ w2[c]  (128 x 128 x 64)
        #pragma unroll
        for (int kt = 0; kt < 4; kt++) {
            wmma::fragment<wmma::matrix_a, 16, 16, 16, __half, wmma::row_major> pf;
            wmma::load_matrix_sync(pf, H1 + (wM * 16) * 72 + kt * 16, 72);
            #pragma unroll
            for (int j = 0; j < 4; j++) {
                wmma::fragment<wmma::matrix_b, 16, 16, 16, __half, wmma::row_major> vf;
                wmma::load_matrix_sync(vf, W2s + (kt * 16) * 136 + wN * 64 + j * 16, 136);
                wmma::mma_sync(acc2[j], pf, vf, acc2[j]);
            }
        }
        __syncthreads();
        // prefetch w2[c+1] (W2 buffer free; overlaps next GEMM1)
        if (c < 7) { load_w2(c + 1); CP_COMMIT(); }
    }

    // epilogue: stage acc2 (fp32) into As region, add b2 + half residual
    float* Cs = (float*)smc;
    #pragma unroll
    for (int j = 0; j < 4; j++)
        wmma::store_matrix_sync(Cs + (wM * 16) * C_STRIDE + wN * 64 + j * 16,
                                acc2[j], C_STRIDE, wmma::mem_row_major);
    __syncthreads();

    #pragma unroll
    for (int q = 0; q < 8; q++) {
        int e = tid + q * 512;
        int row = e >> 5, c4 = (e & 31) * 4;
        size_t roff = (size_t)(M0 + row) * CDIM + c4;
        uint2 ru = *(const uint2*)(resh + roff);
        float2 r0 = __half22float2(*(__half2*)&ru.x);
        float2 r1 = __half22float2(*(__half2*)&ru.y);
        float v[4];
        v[0] = Cs[row * C_STRIDE + c4 + 0] + __ldg(b2 + c4 + 0) + r0.x;
        v[1] = Cs[row * C_STRIDE + c4 + 1] + __ldg(b2 + c4 + 1) + r0.y;
        v[2] = Cs[row * C_STRIDE + c4 + 2] + __ldg(b2 + c4 + 2) + r1.x;
        v[3] = Cs[row * C_STRIDE + c4 + 3] + __ldg(b2 + c4 + 3) + r1.y;
        *(float4*)(out + roff) = *(float4*)v;
    }
}

// ---------------- tensor-core windowed attention (R13 proven) --------------
#define ATT_SMEM 88320

__global__ void __launch_bounds__(256)
attn_kernel(const __half* __restrict__ qkv, __half* __restrict__ o)
{
    extern __shared__ char smc[];
    int*    tok = (int*)smc;
    __half* qh  = (__half*)(smc + 256);
    __half* kh  = qh + 10240;
    __half* vh  = qh + 20480;
    float*  Ss  = (float*)(smc + 61696);
    __half* Ph  = (__half*)(smc + 79104);

    int w = blockIdx.x;
    int bimg = w >> 6, win = w & 63;
    int wr = win >> 3, wc = win & 7;
    int tid = threadIdx.x, wid = tid >> 5, lane = tid & 31;

    if (tid < TWIN) {
        int r = tid / WS, c = tid - r * WS;
        tok[tid] = bimg * (RESO * RESO) + (wr * WS + r) * RESO + (wc * WS + c);
    }
    for (int i = tid; i < 900; i += 256) {
        int u = i % 5;
        int row = 49 + (i / 5) % 15;
        int th = i / 75;
        int tensor = th >> 2, head = th & 3;
        *(uint4*)(qh + tensor * 10240 + head * 2560 + row * 40 + u * 8) =
            make_uint4(0, 0, 0, 0);
    }
    __syncthreads();

    for (int i = tid; i < TWIN * 48; i += 256) {
        int t = i / 48, c = i - t * 48;
        int tensor = c >> 4, head = (c >> 2) & 3, u = c & 3;
        uint4 hv = *(const uint4*)(qkv + (size_t)tok[t] * 384
                                   + tensor * 128 + head * 32 + u * 8);
        *(uint4*)(qh + tensor * 10240 + head * 2560 + t * 40 + u * 8) = hv;
    }
    __syncthreads();

    const float scale = 0.17677669529663687f;
    int wM = wid & 3;
    int wN = wid >> 2;

    for (int head = 0; head < NHEAD; head++) {
        const __half* q = qh + head * 2560;
        const __half* k = kh + head * 2560;
        const __half* v = vh + head * 2560;

        wmma::fragment<wmma::accumulator, 16, 16, 16, float> sa[2];
        wmma::fill_fragment(sa[0], 0.0f);
        wmma::fill_fragment(sa[1], 0.0f);
        #pragma unroll
        for (int kt = 0; kt < 2; kt++) {
            wmma::fragment<wmma::matrix_a, 16, 16, 16, __half, wmma::row_major> af;
            wmma::load_matrix_sync(af, q + (wM * 16) * 40 + kt * 16, 40);
            #pragma unroll
            for (int j = 0; j < 2; j++) {
                wmma::fragment<wmma::matrix_b, 16, 16, 16, __half, wmma::col_major> bf;
                wmma::load_matrix_sync(bf, k + (wN * 32 + j * 16) * 40 + kt * 16, 40);
                wmma::mma_sync(sa[j], af, bf, sa[j]);
            }
        }
        #pragma unroll
        for (int j = 0; j < 2; j++)
            wmma::store_matrix_sync(Ss + (wM * 16) * 68 + wN * 32 + j * 16,
                                    sa[j], 68, wmma::mem_row_major);
        __syncthreads();

        for (int row = wid; row < TWIN; row += 8) {
            float v0 = Ss[row * 68 + lane] * scale;
            float v1 = (lane + 32 < TWIN) ? Ss[row * 68 + lane + 32] * scale : -3.4e38f;
            float m = fmaxf(v0, v1);
            #pragma unroll
            for (int off = 16; off; off >>= 1)
                m = fmaxf(m, __shfl_xor_sync(0xffffffffu, m, off));
            float e0 = __expf(v0 - m);
            float e1 = (lane + 32 < TWIN) ? __expf(v1 - m) : 0.0f;
            float s = e0 + e1;
            #pragma unroll
            for (int off = 16; off; off >>= 1)
                s += __shfl_xor_sync(0xffffffffu, s, off);
            float inv = 1.0f / s;
            Ph[row * 72 + lane]      = __float2half_rn(e0 * inv);
            Ph[row * 72 + lane + 32] = __float2half_rn(e1 * inv);
        }
        if (head == 0) {
            for (int e = tid; e < 15 * 16; e += 256) {
                int r = 49 + (e >> 4), c = (e & 15) * 4;
                *(uint2*)(Ph + r * 72 + c) = make_uint2(0, 0);
            }
        }
        __syncthreads();

        wmma::fragment<wmma::accumulator, 16, 16, 16, float> oa;
        wmma::fill_fragment(oa, 0.0f);
        #pragma unroll
        for (int kt = 0; kt < 4; kt++) {
            wmma::fragment<wmma::matrix_a, 16, 16, 16, __half, wmma::row_major> pf;
            wmma::fragment<wmma::matrix_b, 16, 16, 16, __half, wmma::row_major> vf;
            wmma::load_matrix_sync(pf, Ph + (wM * 16) * 72 + kt * 16, 72);
            wmma::load_matrix_sync(vf, v + (kt * 16) * 40 + wN * 16, 40);
            wmma::mma_sync(oa, pf, vf, oa);
        }
        wmma::store_matrix_sync(Ss + (wM * 16) * 68 + wN * 16, oa, 68,
                                wmma::mem_row_major);
        __syncthreads();

        for (int e = tid; e < TWIN * 16; e += 256) {
            int r = e >> 4, d = (e & 15) * 2;
            __half2 p = __floats2half2_rn(Ss[r * 68 + d], Ss[r * 68 + d + 1]);
            *(__half2*)(o + (size_t)tok[r] * CDIM + head * HDIM + d) = p;
        }
        __syncthreads();
    }
}

// ---------------- launch ----------------
extern "C" void kernel_launch(void* const* d_in, const int* in_sizes, int n_in,
                              void* d_out, int out_size)
{
    const float* x      = (const float*)d_in[0];
    const float* ln1_g  = (const float*)d_in[1];
    const float* ln1_b  = (const float*)d_in[2];
    const float* qkv_w  = (const float*)d_in[3];
    const float* qkv_b  = (const float*)d_in[4];
    const float* proj_w = (const float*)d_in[5];
    const float* proj_b = (const float*)d_in[6];
    const float* ln2_g  = (const float*)d_in[7];
    const float* ln2_b  = (const float*)d_in[8];
    const float* mlp_w1 = (const float*)d_in[9];
    const float* mlp_b1 = (const float*)d_in[10];
    const float* mlp_w2 = (const float*)d_in[11];
    const float* mlp_b2 = (const float*)d_in[12];
    float* out = (float*)d_out;

    __half *p_lnh, *p_qkvh, *p_oh, *p_x2h, *p_wTh;
    cudaGetSymbolAddress((void**)&p_lnh,  g_lnh);
    cudaGetSymbolAddress((void**)&p_qkvh, g_qkvh);
    cudaGetSymbolAddress((void**)&p_oh,   g_oh);
    cudaGetSymbolAddress((void**)&p_x2h,  g_x2h);
    cudaGetSymbolAddress((void**)&p_wTh,  g_wTh);
    __half* wt_qkv  = p_wTh;
    __half* wt_proj = p_wTh + W_QKV_N;
    __half* wt_w1   = p_wTh + W_QKV_N + W_PROJ_N;
    __half* wt_w2   = p_wTh + W_QKV_N + W_PROJ_N + W_W1_N;

    cudaFuncSetAttribute(tc_gemm<EPI_BIAS>,    cudaFuncAttributeMaxDynamicSharedMemorySize, SMEM_BYTES);
    cudaFuncSetAttribute(tc_gemm<EPI_RES_LN2>, cudaFuncAttributeMaxDynamicSharedMemorySize, SMEM_BYTES);
    cudaFuncSetAttribute(fused_mlp,            cudaFuncAttributeMaxDynamicSharedMemorySize, FM_SMEM);
    cudaFuncSetAttribute(attn_kernel,          cudaFuncAttributeMaxDynamicSharedMemorySize, ATT_SMEM);

    const int MT = NTOK / 128;  // 784

    // 0. fused prep: weight->half + LN1->half
    prep_kernel<<<W_BLOCKS + LN_BLOCKS, 256>>>(qkv_w, proj_w, mlp_w1, mlp_w2, p_wTh,
                                               x, ln1_g, ln1_b, p_lnh);
    // 1. QKV = ln1 @ qkv_w + qkv_b  -> half
    tc_gemm<EPI_BIAS><<<dim3(3, MT), 256, SMEM_BYTES>>>(
        p_lnh, wt_qkv, qkv_b, nullptr, p_qkvh, 3 * CDIM, CDIM,
        nullptr, nullptr, nullptr);
    // 2. attention (tensor cores; one block per window)
    attn_kernel<<<NWIN, 256, ATT_SMEM>>>(p_qkvh, p_oh);
    // 3. x2 = x + proj(o) -> half ; fused LN2 -> half
    tc_gemm<EPI_RES_LN2><<<dim3(1, MT), 256, SMEM_BYTES>>>(
        p_oh, wt_proj, proj_b, x, p_x2h, CDIM, CDIM,
        ln2_g, ln2_b, p_lnh);
    // 4. fused MLP: out = x2 + gelu(ln2@w1+b1)@w2 + b2
    fused_mlp<<<MT, 512, FM_SMEM>>>(p_lnh, wt_w1, mlp_b1, wt_w2, mlp_b2, p_x2h, out);
}

// round 15
// speedup vs baseline: 1.1407x; 1.1407x over previous
#include <cuda_runtime.h>
#include <cuda_fp16.h>
#include <mma.h>
#include <math.h>
#include <stdint.h>

using namespace nvcuda;

// ---------------- problem constants ----------------
#define RESO 56
#define WS   7
#define CDIM 128
#define NHEAD 4
#define HDIM 32
#define HID  512
#define BATCH 32
#define NTOK (BATCH * RESO * RESO)      // 100352
#define NWIN (BATCH * 8 * 8)            // 2048 windows
#define TWIN 49

#define W_QKV_N 49152
#define W_PROJ_N 16384
#define W_W1_N 65536
#define W_W2_N 65536
#define W_TOTAL (W_QKV_N + W_PROJ_N + W_W1_N + W_W2_N)
#define W_BLOCKS ((W_TOTAL + 255) / 256)          // 769
#define LN_BLOCKS ((NTOK * 32) / 256)             // 12544

// ---------------- device scratch ----------------
__device__ __half g_lnh[(size_t)NTOK * CDIM];
__device__ __half g_qkvh[(size_t)NTOK * 3 * CDIM];
__device__ __half g_oh [(size_t)NTOK * CDIM];
__device__ __half g_x2h[(size_t)NTOK * CDIM];
__device__ __half g_h1h[(size_t)NTOK * HID];
__device__ __half g_wTh[W_TOTAL];

__device__ __forceinline__ uint32_t smem_u32(const void* p) {
    uint32_t a;
    asm("{ .reg .u64 t; cvta.to.shared.u64 t, %1; cvt.u32.u64 %0, t; }" : "=r"(a) : "l"(p));
    return a;
}
__device__ __forceinline__ void cp_async16(uint32_t saddr, const void* gaddr) {
    asm volatile("cp.async.ca.shared.global [%0], [%1], 16;" :: "r"(saddr), "l"(gaddr));
}
#define CP_COMMIT() asm volatile("cp.async.commit_group;" ::: "memory")
#define CP_WAIT(n)  asm volatile("cp.async.wait_group %0;" :: "n"(n) : "memory")

__device__ __forceinline__ void store_half4(__half* dst, float a, float b, float c, float d) {
    __half2 h01 = __floats2half2_rn(a, b);
    __half2 h23 = __floats2half2_rn(c, d);
    uint2 u;
    u.x = *(uint32_t*)&h01;
    u.y = *(uint32_t*)&h23;
    *(uint2*)dst = u;
}

// ---------------- fused prep: weight->half + LN1->half ----------------
__global__ void prep_kernel(const float* __restrict__ w0, const float* __restrict__ w1,
                            const float* __restrict__ w2, const float* __restrict__ w3,
                            __half* __restrict__ WT,
                            const float* __restrict__ x, const float* __restrict__ g,
                            const float* __restrict__ b, __half* __restrict__ out)
{
    if (blockIdx.x < W_BLOCKS) {
        int idx = blockIdx.x * 256 + threadIdx.x;
        if (idx >= W_TOTAL) return;
        float v;
        if (idx < W_QKV_N)                          v = w0[idx];
        else if (idx < W_QKV_N + W_PROJ_N)          v = w1[idx - W_QKV_N];
        else if (idx < W_QKV_N + W_PROJ_N + W_W1_N) v = w2[idx - W_QKV_N - W_PROJ_N];
        else                                        v = w3[idx - W_QKV_N - W_PROJ_N - W_W1_N];
        WT[idx] = __float2half_rn(v);
        return;
    }
    int gwarp = ((blockIdx.x - W_BLOCKS) * 256 + threadIdx.x) >> 5;
    int lane  = threadIdx.x & 31;
    if (gwarp >= NTOK) return;
    float4 v = ((const float4*)(x + (size_t)gwarp * CDIM))[lane];
    float s  = v.x + v.y + v.z + v.w;
    float ss = v.x*v.x + v.y*v.y + v.z*v.z + v.w*v.w;
    #pragma unroll
    for (int off = 16; off; off >>= 1) {
        s  += __shfl_xor_sync(0xffffffffu, s,  off);
        ss += __shfl_xor_sync(0xffffffffu, ss, off);
    }
    float mean = s * (1.0f / CDIM);
    float var  = ss * (1.0f / CDIM) - mean * mean;
    float rstd = rsqrtf(var + 1e-5f);
    float4 gg = ((const float4*)g)[lane];
    float4 bb = ((const float4*)b)[lane];
    store_half4(out + (size_t)gwarp * CDIM + lane * 4,
                (v.x - mean) * rstd * gg.x + bb.x,
                (v.y - mean) * rstd * gg.y + bb.y,
                (v.z - mean) * rstd * gg.z + bb.z,
                (v.w - mean) * rstd * gg.w + bb.w);
}

// ---------------- fp16 WMMA GEMM: K-chunks of 64, double-buffered ----------
enum { EPI_BIAS = 0, EPI_GELU = 2, EPI_RES_LN2 = 3, EPI_BIAS_RESH = 4 };

#define AH_STRIDE 72    // halves (64 + 8 pad)
#define BH_STRIDE 136   // halves
#define C_STRIDE  132   // floats (epilogue staging)
#define ABUFH (128 * AH_STRIDE * 2)     // 18432 B
#define BBUFH (64 * BH_STRIDE * 2)      // 17408 B
#define SMEM_BYTES (2 * (ABUFH + BBUFH))// 71680 B (> 67584 epilogue)

template <int EPI>
__global__ void __launch_bounds__(256, 2)
tc_gemm(const __half* __restrict__ A, const __half* __restrict__ B,
        const float* __restrict__ bias, const float* __restrict__ res,
        const __half* __restrict__ resh,
        float* __restrict__ Cf, __half* __restrict__ Ch, int N, int K,
        const float* __restrict__ lng, const float* __restrict__ lnb,
        __half* __restrict__ C2)
{
    extern __shared__ char smem[];
    uint32_t sbase = smem_u32(smem);
    const int tid = threadIdx.x;
    const int wid = tid >> 5;
    const int warpM = wid & 1;
    const int warpN = wid >> 1;
    const int M0 = blockIdx.y * 128;
    const int N0 = blockIdx.x * 128;

    const __half* Abase = A + (size_t)M0 * K;
    const __half* Bbase = B + N0;
    const int nchunk = K >> 6;

    wmma::fragment<wmma::accumulator, 16, 16, 16, float> acc[4][2];
    #pragma unroll
    for (int i = 0; i < 4; i++)
        #pragma unroll
        for (int j = 0; j < 2; j++) wmma::fill_fragment(acc[i][j], 0.0f);

    auto load_chunk = [&](int c) {
        int buf = c & 1;
        uint32_t sa = sbase + buf * ABUFH;
        uint32_t sb = sbase + 2 * ABUFH + buf * BBUFH;
        int k0 = c << 6;
        #pragma unroll
        for (int q = 0; q < 4; q++) {       // A: 1024 x 16B chunks (128 x 64 h)
            int e = tid + q * 256;
            int row = e >> 3, c8 = (e & 7) * 8;
            cp_async16(sa + (row * AH_STRIDE + c8) * 2,
                       Abase + (size_t)row * K + k0 + c8);
        }
        #pragma unroll
        for (int q = 0; q < 4; q++) {       // B: 1024 x 16B chunks (64 x 128 h)
            int e = tid + q * 256;
            int row = e >> 4, c8 = (e & 15) * 8;
            cp_async16(sb + (row * BH_STRIDE + c8) * 2,
                       Bbase + (size_t)(k0 + row) * N + c8);
        }
    };

    load_chunk(0);
    CP_COMMIT();

    for (int c = 0; c < nchunk; c++) {
        if (c + 1 < nchunk) {
            load_chunk(c + 1);
            CP_COMMIT();
            CP_WAIT(1);
        } else {
            CP_WAIT(0);
        }
        __syncthreads();

        int buf = c & 1;
        const __half* As = (const __half*)(smem + buf * ABUFH);
        const __half* Bs = (const __half*)(smem + 2 * ABUFH + buf * BBUFH);
        #pragma unroll
        for (int ks = 0; ks < 4; ks++) {
            wmma::fragment<wmma::matrix_a, 16, 16, 16, __half, wmma::row_major> af[4];
            wmma::fragment<wmma::matrix_b, 16, 16, 16, __half, wmma::row_major> bf[2];
            #pragma unroll
            for (int i = 0; i < 4; i++)
                wmma::load_matrix_sync(af[i],
                    As + (warpM * 64 + i * 16) * AH_STRIDE + ks * 16, AH_STRIDE);
            #pragma unroll
            for (int j = 0; j < 2; j++)
                wmma::load_matrix_sync(bf[j],
                    Bs + (ks * 16) * BH_STRIDE + warpN * 32 + j * 16, BH_STRIDE);
            #pragma unroll
            for (int i = 0; i < 4; i++)
                #pragma unroll
                for (int j = 0; j < 2; j++)
                    wmma::mma_sync(acc[i][j], af[i], bf[j], acc[i][j]);
        }
        __syncthreads();
    }

    float* Cs = (float*)smem;
    #pragma unroll
    for (int i = 0; i < 4; i++)
        #pragma unroll
        for (int j = 0; j < 2; j++)
            wmma::store_matrix_sync(
                Cs + (warpM * 64 + i * 16) * C_STRIDE + warpN * 32 + j * 16,
                acc[i][j], C_STRIDE, wmma::mem_row_major);
    __syncthreads();

    #pragma unroll
    for (int e0 = 0; e0 < 16; e0++) {
        int e = tid + e0 * 256;
        int row = e >> 5;
        int c4  = (e & 31) * 4;
        size_t roff = (size_t)(M0 + row) * N + N0 + c4;
        float rv[4] = {0, 0, 0, 0};
        if (EPI == EPI_BIAS_RESH) {
            uint2 ru = *(const uint2*)(resh + roff);
            float2 r0 = __half22float2(*(__half2*)&ru.x);
            float2 r1 = __half22float2(*(__half2*)&ru.y);
            rv[0] = r0.x; rv[1] = r0.y; rv[2] = r1.x; rv[3] = r1.y;
        }
        float v[4];
        #pragma unroll
        for (int q = 0; q < 4; q++) {
            float t = Cs[row * C_STRIDE + c4 + q] + __ldg(bias + N0 + c4 + q);
            if (EPI == EPI_RES_LN2) t += res[roff + q];
            if (EPI == EPI_BIAS_RESH) t += rv[q];
            if (EPI == EPI_GELU)
                t = 0.5f * t * (1.0f + erff(t * 0.70710678118654752f));
            v[q] = t;
        }
        if (EPI == EPI_BIAS_RESH) {
            *(float4*)(Cf + roff) = *(float4*)v;
        } else {
            store_half4(Ch + roff, v[0], v[1], v[2], v[3]);
        }
        if (EPI == EPI_RES_LN2) {
            float s  = v[0] + v[1] + v[2] + v[3];
            float ss = v[0]*v[0] + v[1]*v[1] + v[2]*v[2] + v[3]*v[3];
            #pragma unroll
            for (int off = 16; off; off >>= 1) {
                s  += __shfl_xor_sync(0xffffffffu, s,  off);
                ss += __shfl_xor_sync(0xffffffffu, ss, off);
            }
            float mean = s * (1.0f / CDIM);
            float var  = ss * (1.0f / CDIM) - mean * mean;
            float rstd = rsqrtf(var + 1e-5f);
            store_half4(C2 + roff,
                        (v[0] - mean) * rstd * __ldg(lng + c4 + 0) + __ldg(lnb + c4 + 0),
                        (v[1] - mean) * rstd * __ldg(lng + c4 + 1) + __ldg(lnb + c4 + 1),
                        (v[2] - mean) * rstd * __ldg(lng + c4 + 2) + __ldg(lnb + c4 + 2),
                        (v[3] - mean) * rstd * __ldg(lng + c4 + 3) + __ldg(lnb + c4 + 3));
        }
    }
}

// ---------------- tensor-core windowed attention (R13 proven) --------------
#define ATT_SMEM 88320

__global__ void __launch_bounds__(256)
attn_kernel(const __half* __restrict__ qkv, __half* __restrict__ o)
{
    extern __shared__ char smc[];
    int*    tok = (int*)smc;
    __half* qh  = (__half*)(smc + 256);
    __half* kh  = qh + 10240;
    __half* vh  = qh + 20480;
    float*  Ss  = (float*)(smc + 61696);
    __half* Ph  = (__half*)(smc + 79104);

    int w = blockIdx.x;
    int bimg = w >> 6, win = w & 63;
    int wr = win >> 3, wc = win & 7;
    int tid = threadIdx.x, wid = tid >> 5, lane = tid & 31;

    if (tid < TWIN) {
        int r = tid / WS, c = tid - r * WS;
        tok[tid] = bimg * (RESO * RESO) + (wr * WS + r) * RESO + (wc * WS + c);
    }
    for (int i = tid; i < 900; i += 256) {
        int u = i % 5;
        int row = 49 + (i / 5) % 15;
        int th = i / 75;
        int tensor = th >> 2, head = th & 3;
        *(uint4*)(qh + tensor * 10240 + head * 2560 + row * 40 + u * 8) =
            make_uint4(0, 0, 0, 0);
    }
    __syncthreads();

    for (int i = tid; i < TWIN * 48; i += 256) {
        int t = i / 48, c = i - t * 48;
        int tensor = c >> 4, head = (c >> 2) & 3, u = c & 3;
        uint4 hv = *(const uint4*)(qkv + (size_t)tok[t] * 384
                                   + tensor * 128 + head * 32 + u * 8);
        *(uint4*)(qh + tensor * 10240 + head * 2560 + t * 40 + u * 8) = hv;
    }
    __syncthreads();

    const float scale = 0.17677669529663687f;
    int wM = wid & 3;
    int wN = wid >> 2;

    for (int head = 0; head < NHEAD; head++) {
        const __half* q = qh + head * 2560;
        const __half* k = kh + head * 2560;
        const __half* v = vh + head * 2560;

        wmma::fragment<wmma::accumulator, 16, 16, 16, float> sa[2];
        wmma::fill_fragment(sa[0], 0.0f);
        wmma::fill_fragment(sa[1], 0.0f);
        #pragma unroll
        for (int kt = 0; kt < 2; kt++) {
            wmma::fragment<wmma::matrix_a, 16, 16, 16, __half, wmma::row_major> af;
            wmma::load_matrix_sync(af, q + (wM * 16) * 40 + kt * 16, 40);
            #pragma unroll
            for (int j = 0; j < 2; j++) {
                wmma::fragment<wmma::matrix_b, 16, 16, 16, __half, wmma::col_major> bf;
                wmma::load_matrix_sync(bf, k + (wN * 32 + j * 16) * 40 + kt * 16, 40);
                wmma::mma_sync(sa[j], af, bf, sa[j]);
            }
        }
        #pragma unroll
        for (int j = 0; j < 2; j++)
            wmma::store_matrix_sync(Ss + (wM * 16) * 68 + wN * 32 + j * 16,
                                    sa[j], 68, wmma::mem_row_major);
        __syncthreads();

        for (int row = wid; row < TWIN; row += 8) {
            float v0 = Ss[row * 68 + lane] * scale;
            float v1 = (lane + 32 < TWIN) ? Ss[row * 68 + lane + 32] * scale : -3.4e38f;
            float m = fmaxf(v0, v1);
            #pragma unroll
            for (int off = 16; off; off >>= 1)
                m = fmaxf(m, __shfl_xor_sync(0xffffffffu, m, off));
            float e0 = __expf(v0 - m);
            float e1 = (lane + 32 < TWIN) ? __expf(v1 - m) : 0.0f;
            float s = e0 + e1;
            #pragma unroll
            for (int off = 16; off; off >>= 1)
                s += __shfl_xor_sync(0xffffffffu, s, off);
            float inv = 1.0f / s;
            Ph[row * 72 + lane]      = __float2half_rn(e0 * inv);
            Ph[row * 72 + lane + 32] = __float2half_rn(e1 * inv);
        }
        if (head == 0) {
            for (int e = tid; e < 15 * 16; e += 256) {
                int r = 49 + (e >> 4), c = (e & 15) * 4;
                *(uint2*)(Ph + r * 72 + c) = make_uint2(0, 0);
            }
        }
        __syncthreads();

        wmma::fragment<wmma::accumulator, 16, 16, 16, float> oa;
        wmma::fill_fragment(oa, 0.0f);
        #pragma unroll
        for (int kt = 0; kt < 4; kt++) {
            wmma::fragment<wmma::matrix_a, 16, 16, 16, __half, wmma::row_major> pf;
            wmma::fragment<wmma::matrix_b, 16, 16, 16, __half, wmma::row_major> vf;
            wmma::load_matrix_sync(pf, Ph + (wM * 16) * 72 + kt * 16, 72);
            wmma::load_matrix_sync(vf, v + (kt * 16) * 40 + wN * 16, 40);
            wmma::mma_sync(oa, pf, vf, oa);
        }
        wmma::store_matrix_sync(Ss + (wM * 16) * 68 + wN * 16, oa, 68,
                                wmma::mem_row_major);
        __syncthreads();

        for (int e = tid; e < TWIN * 16; e += 256) {
            int r = e >> 4, d = (e & 15) * 2;
            __half2 p = __floats2half2_rn(Ss[r * 68 + d], Ss[r * 68 + d + 1]);
            *(__half2*)(o + (size_t)tok[r] * CDIM + head * HDIM + d) = p;
        }
        __syncthreads();
    }
}

// ---------------- launch ----------------
extern "C" void kernel_launch(void* const* d_in, const int* in_sizes, int n_in,
                              void* d_out, int out_size)
{
    const float* x      = (const float*)d_in[0];
    const float* ln1_g  = (const float*)d_in[1];
    const float* ln1_b  = (const float*)d_in[2];
    const float* qkv_w  = (const float*)d_in[3];
    const float* qkv_b  = (const float*)d_in[4];
    const float* proj_w = (const float*)d_in[5];
    const float* proj_b = (const float*)d_in[6];
    const float* ln2_g  = (const float*)d_in[7];
    const float* ln2_b  = (const float*)d_in[8];
    const float* mlp_w1 = (const float*)d_in[9];
    const float* mlp_b1 = (const float*)d_in[10];
    const float* mlp_w2 = (const float*)d_in[11];
    const float* mlp_b2 = (const float*)d_in[12];
    float* out = (float*)d_out;

    __half *p_lnh, *p_qkvh, *p_oh, *p_x2h, *p_h1h, *p_wTh;
    cudaGetSymbolAddress((void**)&p_lnh,  g_lnh);
    cudaGetSymbolAddress((void**)&p_qkvh, g_qkvh);
    cudaGetSymbolAddress((void**)&p_oh,   g_oh);
    cudaGetSymbolAddress((void**)&p_x2h,  g_x2h);
    cudaGetSymbolAddress((void**)&p_h1h,  g_h1h);
    cudaGetSymbolAddress((void**)&p_wTh,  g_wTh);
    __half* wt_qkv  = p_wTh;
    __half* wt_proj = p_wTh + W_QKV_N;
    __half* wt_w1   = p_wTh + W_QKV_N + W_PROJ_N;
    __half* wt_w2   = p_wTh + W_QKV_N + W_PROJ_N + W_W1_N;

    cudaFuncSetAttribute(tc_gemm<EPI_BIAS>,      cudaFuncAttributeMaxDynamicSharedMemorySize, SMEM_BYTES);
    cudaFuncSetAttribute(tc_gemm<EPI_GELU>,      cudaFuncAttributeMaxDynamicSharedMemorySize, SMEM_BYTES);
    cudaFuncSetAttribute(tc_gemm<EPI_RES_LN2>,   cudaFuncAttributeMaxDynamicSharedMemorySize, SMEM_BYTES);
    cudaFuncSetAttribute(tc_gemm<EPI_BIAS_RESH>, cudaFuncAttributeMaxDynamicSharedMemorySize, SMEM_BYTES);
    cudaFuncSetAttribute(attn_kernel,            cudaFuncAttributeMaxDynamicSharedMemorySize, ATT_SMEM);

    const int MT = NTOK / 128;  // 784

    // 0. fused prep: weight->half + LN1->half
    prep_kernel<<<W_BLOCKS + LN_BLOCKS, 256>>>(qkv_w, proj_w, mlp_w1, mlp_w2, p_wTh,
                                               x, ln1_g, ln1_b, p_lnh);
    // 1. QKV = ln1 @ qkv_w + qkv_b  -> half
    tc_gemm<EPI_BIAS><<<dim3(3, MT), 256, SMEM_BYTES>>>(
        p_lnh, wt_qkv, qkv_b, nullptr, nullptr, nullptr, p_qkvh, 3 * CDIM, CDIM,
        nullptr, nullptr, nullptr);
    // 2. attention (tensor cores; one block per window)
    attn_kernel<<<NWIN, 256, ATT_SMEM>>>(p_qkvh, p_oh);
    // 3. x2 = x + proj(o) -> half ; fused LN2 -> half
    tc_gemm<EPI_RES_LN2><<<dim3(1, MT), 256, SMEM_BYTES>>>(
        p_oh, wt_proj, proj_b, x, nullptr, nullptr, p_x2h, CDIM, CDIM,
        ln2_g, ln2_b, p_lnh);
    // 4. h1 = gelu(ln2 @ w1 + b1) -> half
    tc_gemm<EPI_GELU><<<dim3(4, MT), 256, SMEM_BYTES>>>(
        p_lnh, wt_w1, mlp_b1, nullptr, nullptr, nullptr, p_h1h, HID, CDIM,
        nullptr, nullptr, nullptr);
    // 5. out = x2 + h1 @ w2 + b2  (fp32 out, half residual)
    tc_gemm<EPI_BIAS_RESH><<<dim3(1, MT), 256, SMEM_BYTES>>>(
        p_h1h, wt_w2, mlp_b2, nullptr, p_x2h, out, nullptr, CDIM, HID,
        nullptr, nullptr, nullptr);
}